// round 1
// baseline (speedup 1.0000x reference)
#include <cuda_runtime.h>
#include <cstdint>

#define N_NODES 50000
#define N_EDGES 800000
#define D_IN    256
#define D_OUT   128
#define EPSV    1e-9f

// Scratch (allocation-free rule: __device__ globals)
__device__ float g_Z [(size_t)N_NODES * D_OUT];   // Z  = feat @ W1   [N, 128]
__device__ float g_H1[(size_t)N_NODES * D_OUT];   // H1 = A @ Z       [N, 128]

// ---------------- packed f32x2 helpers (Blackwell) ----------------
__device__ __forceinline__ unsigned long long pack2(float v) {
    unsigned long long r;
    asm("mov.b64 %0, {%1, %2};" : "=l"(r) : "f"(v), "f"(v));
    return r;
}
__device__ __forceinline__ void unpack2(unsigned long long v, float& lo, float& hi) {
    asm("mov.b64 {%0, %1}, %2;" : "=f"(lo), "=f"(hi) : "l"(v));
}
__device__ __forceinline__ void fma2(unsigned long long& d, unsigned long long a, unsigned long long b) {
    asm("fma.rn.f32x2 %0, %1, %2, %0;" : "+l"(d) : "l"(a), "l"(b));
}

// ---------------- zero H1 ----------------
__global__ void zero_h1_kernel() {
    int idx = blockIdx.x * blockDim.x + threadIdx.x;       // float4 index
    const int total = N_NODES * D_OUT / 4;                 // 1,600,000
    if (idx < total) {
        float4 z = make_float4(0.f, 0.f, 0.f, 0.f);
        reinterpret_cast<float4*>(g_H1)[idx] = z;
    }
}

// ---------------- fused GEMM: out[:, :128] = LN(relu(feat@W0+b0)); g_Z = feat@W1 ----------------
// Block: 256 threads (8 warps), TM=64 rows, full N=256 (128 f0 | 128 Z), K tiled by 64.
#define TM 64
#define KC 64
#define XSTRIDE 68
#define GEMM_SMEM ((KC*256 + TM*XSTRIDE) * 4)   // 82944 B

__global__ void __launch_bounds__(256, 2)
gemm_fused_kernel(const float* __restrict__ feat,
                  const float* __restrict__ W0, const float* __restrict__ b0,
                  const float* __restrict__ scale0, const float* __restrict__ offset0,
                  const float* __restrict__ W1,
                  float* __restrict__ out)
{
    extern __shared__ float smem[];
    float* Ws = smem;                 // [KC][256]
    float* Xs = smem + KC * 256;      // [TM][XSTRIDE]

    const int tid  = threadIdx.x;
    const int warp = tid >> 5;
    const int lane = tid & 31;
    const int row0 = blockIdx.x * TM;

    // acc pairs: [8 rows][4 pair-slots]; slot j holds cols {2*(lane+32j), 2*(lane+32j)+1}
    unsigned long long acc[8][4];
#pragma unroll
    for (int r = 0; r < 8; ++r)
#pragma unroll
        for (int j = 0; j < 4; ++j) acc[r][j] = 0ull;

    for (int kc = 0; kc < D_IN / KC; ++kc) {
        // load W chunk: Ws[k][n] = n<128 ? W0[kg][n] : W1[kg][n-128]
        for (int i = tid; i < (KC * 256) / 4; i += 256) {
            int k  = i >> 6;
            int n4 = (i & 63) * 4;
            int kg = kc * KC + k;
            float4 v;
            if (n4 < 128) v = *reinterpret_cast<const float4*>(W0 + (size_t)kg * 128 + n4);
            else          v = *reinterpret_cast<const float4*>(W1 + (size_t)kg * 128 + (n4 - 128));
            *reinterpret_cast<float4*>(&Ws[k * 256 + n4]) = v;
        }
        // load X tile: Xs[r][c] = feat[row0+r][kc*64+c]
        for (int i = tid; i < (TM * KC) / 4; i += 256) {
            int r  = i >> 4;
            int c4 = (i & 15) * 4;
            int grow = row0 + r;
            float4 v = make_float4(0.f, 0.f, 0.f, 0.f);
            if (grow < N_NODES)
                v = *reinterpret_cast<const float4*>(feat + (size_t)grow * D_IN + kc * KC + c4);
            *reinterpret_cast<float4*>(&Xs[r * XSTRIDE + c4]) = v;
        }
        __syncthreads();

        const float* xbase = Xs + (warp * 8) * XSTRIDE;
#pragma unroll 4
        for (int k = 0; k < KC; ++k) {
            const float* wrow = Ws + k * 256;
            unsigned long long w0 = *reinterpret_cast<const unsigned long long*>(wrow + 2 * lane);
            unsigned long long w1 = *reinterpret_cast<const unsigned long long*>(wrow + 64 + 2 * lane);
            unsigned long long w2 = *reinterpret_cast<const unsigned long long*>(wrow + 128 + 2 * lane);
            unsigned long long w3 = *reinterpret_cast<const unsigned long long*>(wrow + 192 + 2 * lane);
#pragma unroll
            for (int rr = 0; rr < 8; ++rr) {
                unsigned long long x2 = pack2(xbase[rr * XSTRIDE + k]);
                fma2(acc[rr][0], x2, w0);
                fma2(acc[rr][1], x2, w1);
                fma2(acc[rr][2], x2, w2);
                fma2(acc[rr][3], x2, w3);
            }
        }
        __syncthreads();
    }

    // ---- epilogue ----
    // per-lane column params for f0 (cols 2l,2l+1 and 64+2l,65+2l)
    float2 bA = *reinterpret_cast<const float2*>(b0 + 2 * lane);
    float2 bB = *reinterpret_cast<const float2*>(b0 + 64 + 2 * lane);
    float2 sA = *reinterpret_cast<const float2*>(scale0 + 2 * lane);
    float2 sB = *reinterpret_cast<const float2*>(scale0 + 64 + 2 * lane);
    float2 oA = *reinterpret_cast<const float2*>(offset0 + 2 * lane);
    float2 oB = *reinterpret_cast<const float2*>(offset0 + 64 + 2 * lane);

#pragma unroll
    for (int rr = 0; rr < 8; ++rr) {
        int row = row0 + warp * 8 + rr;
        float a0, a1, a2, a3;
        unpack2(acc[rr][0], a0, a1);
        unpack2(acc[rr][1], a2, a3);
        a0 = fmaxf(a0 + bA.x, 0.f);
        a1 = fmaxf(a1 + bA.y, 0.f);
        a2 = fmaxf(a2 + bB.x, 0.f);
        a3 = fmaxf(a3 + bB.y, 0.f);
        float s = a0 + a1 + a2 + a3;
        float q = a0 * a0 + a1 * a1 + a2 * a2 + a3 * a3;
#pragma unroll
        for (int off = 16; off > 0; off >>= 1) {
            s += __shfl_xor_sync(0xffffffffu, s, off);
            q += __shfl_xor_sync(0xffffffffu, q, off);
        }
        float mean = s * (1.f / 128.f);
        float var  = q * (1.f / 128.f) - mean * mean;
        float inv  = rsqrtf(var + EPSV);
        if (row < N_NODES) {
            float2 w;
            w.x = (a0 - mean) * inv * sA.x + oA.x;
            w.y = (a1 - mean) * inv * sA.y + oA.y;
            *reinterpret_cast<float2*>(out + (size_t)row * 256 + 2 * lane) = w;
            w.x = (a2 - mean) * inv * sB.x + oB.x;
            w.y = (a3 - mean) * inv * sB.y + oB.y;
            *reinterpret_cast<float2*>(out + (size_t)row * 256 + 64 + 2 * lane) = w;
            // Z raw (pre-bias/relu): slot2 -> cols 2l,2l+1 ; slot3 -> cols 64+2l,65+2l
            *reinterpret_cast<unsigned long long*>(g_Z + (size_t)row * 128 + 2 * lane) = acc[rr][2];
            *reinterpret_cast<unsigned long long*>(g_Z + (size_t)row * 128 + 64 + 2 * lane) = acc[rr][3];
        }
    }
}

// ---------------- SpMM: H1[r] += val * Z[c], one warp per edge, D=128 ----------------
__global__ void __launch_bounds__(256)
spmm_kernel(const int* __restrict__ erow, const int* __restrict__ ecol,
            const float* __restrict__ eval)
{
    int e = blockIdx.x * 8 + (threadIdx.x >> 5);
    if (e >= N_EDGES) return;
    int lane = threadIdx.x & 31;
    int r = __ldg(erow + e);
    int c = __ldg(ecol + e);
    float v = __ldg(eval + e);
    float4 z = *reinterpret_cast<const float4*>(g_Z + (size_t)c * 128 + lane * 4);
    float4 m;
    m.x = v * z.x; m.y = v * z.y; m.z = v * z.z; m.w = v * z.w;
    float* dst = g_H1 + (size_t)r * 128 + lane * 4;
    asm volatile("red.global.add.v4.f32 [%0], {%1, %2, %3, %4};"
                 :: "l"(dst), "f"(m.x), "f"(m.y), "f"(m.z), "f"(m.w) : "memory");
}

// ---------------- f1 epilogue: out[:, 128:] = LN(relu(H1 + b1)) ----------------
__global__ void __launch_bounds__(256)
ln1_kernel(const float* __restrict__ b1, const float* __restrict__ scale1,
           const float* __restrict__ offset1, float* __restrict__ out)
{
    int row = blockIdx.x * 8 + (threadIdx.x >> 5);
    if (row >= N_NODES) return;
    int lane = threadIdx.x & 31;
    float4 h = *reinterpret_cast<const float4*>(g_H1 + (size_t)row * 128 + lane * 4);
    float4 b = *reinterpret_cast<const float4*>(b1 + lane * 4);
    h.x = fmaxf(h.x + b.x, 0.f);
    h.y = fmaxf(h.y + b.y, 0.f);
    h.z = fmaxf(h.z + b.z, 0.f);
    h.w = fmaxf(h.w + b.w, 0.f);
    float s = h.x + h.y + h.z + h.w;
    float q = h.x * h.x + h.y * h.y + h.z * h.z + h.w * h.w;
#pragma unroll
    for (int off = 16; off > 0; off >>= 1) {
        s += __shfl_xor_sync(0xffffffffu, s, off);
        q += __shfl_xor_sync(0xffffffffu, q, off);
    }
    float mean = s * (1.f / 128.f);
    float var  = q * (1.f / 128.f) - mean * mean;
    float inv  = rsqrtf(var + EPSV);
    float4 sc = *reinterpret_cast<const float4*>(scale1 + lane * 4);
    float4 of = *reinterpret_cast<const float4*>(offset1 + lane * 4);
    float4 w;
    w.x = (h.x - mean) * inv * sc.x + of.x;
    w.y = (h.y - mean) * inv * sc.y + of.y;
    w.z = (h.z - mean) * inv * sc.z + of.z;
    w.w = (h.w - mean) * inv * sc.w + of.w;
    *reinterpret_cast<float4*>(out + (size_t)row * 256 + 128 + lane * 4) = w;
}

extern "C" void kernel_launch(void* const* d_in, const int* in_sizes, int n_in,
                              void* d_out, int out_size)
{
    const float* feat    = (const float*)d_in[0];
    const float* W0      = (const float*)d_in[1];
    const float* b0      = (const float*)d_in[2];
    const float* scale0  = (const float*)d_in[3];
    const float* offset0 = (const float*)d_in[4];
    const float* W1      = (const float*)d_in[5];
    const float* b1      = (const float*)d_in[6];
    const float* scale1  = (const float*)d_in[7];
    const float* offset1 = (const float*)d_in[8];
    const int*   erow    = (const int*)d_in[9];
    const int*   ecol    = (const int*)d_in[10];
    const float* eval    = (const float*)d_in[11];
    float* out = (float*)d_out;

    cudaFuncSetAttribute(gemm_fused_kernel,
                         cudaFuncAttributeMaxDynamicSharedMemorySize, GEMM_SMEM);

    zero_h1_kernel<<<(N_NODES * D_OUT / 4 + 255) / 256, 256>>>();
    gemm_fused_kernel<<<(N_NODES + TM - 1) / TM, 256, GEMM_SMEM>>>(
        feat, W0, b0, scale0, offset0, W1, out);
    spmm_kernel<<<(N_EDGES + 7) / 8, 256>>>(erow, ecol, eval);
    ln1_kernel<<<(N_NODES + 7) / 8, 256>>>(b1, scale1, offset1, out);
}